// round 3
// baseline (speedup 1.0000x reference)
#include <cuda_runtime.h>
#include <cuda_bf16.h>
#include <math.h>

#define N_NODES    524288
#define NUM_GRAPHS 8192
#define HDIM       256

// ---------------- scratch (static device globals; no allocation) ----------------
__device__ float g_s[N_NODES];                    // per-node attention score
__device__ int   g_start[NUM_GRAPHS + 1];         // segment starts
__device__ float g_pooled[NUM_GRAPHS * 768];      // [mean | max | weighted]
__device__ float g_Wf[768 * 512];                 // fused blockdiag(Wm,Wx,Ww)@Wc1
__device__ float g_bf[512];                       // fused bias
__device__ float g_hid[NUM_GRAPHS * 512];         // gelu hidden

// ---------------- segment starts from sorted batch (int32!) ----------------
__global__ void seg_start_kernel(const int* __restrict__ batch) {
    int n = blockIdx.x * blockDim.x + threadIdx.x;
    if (n >= N_NODES) return;
    int b  = batch[n];
    int pb = (n == 0) ? -1 : batch[n - 1];
    // clamp defensively so a malformed batch can never write OOB
    if (b >= NUM_GRAPHS) b = NUM_GRAPHS - 1;
    if (pb < -1) pb = -1;
    if (pb > b)  pb = b;
    for (int g = pb + 1; g <= b; g++) g_start[g] = n;
    if (n == N_NODES - 1)
        for (int g = b + 1; g <= NUM_GRAPHS; g++) g_start[g] = N_NODES;
}

// ---------------- node attention scores: s = tanh(x@W1+b1)@W2 + b2 ----------------
// SGEMM 128x128 tile, K=256, 256 threads, 8x8 register tile, fused tanh+reduce epilogue.
__global__ __launch_bounds__(256)
void score_kernel(const float* __restrict__ x, const float* __restrict__ W1,
                  const float* __restrict__ b1, const float* __restrict__ W2,
                  const float* __restrict__ b2v, float* __restrict__ s_out)
{
    __shared__ float As[16][132];
    __shared__ float Bs[16][128];
    __shared__ float psum[128][17];

    int tid = threadIdx.x;
    int tx = tid & 15, ty = tid >> 4;
    const float* Ab = x + (size_t)blockIdx.x * 128 * 256;

    float acc[8][8];
    #pragma unroll
    for (int i = 0; i < 8; i++)
        #pragma unroll
        for (int j = 0; j < 8; j++) acc[i][j] = 0.f;

    int ar = tid >> 2, ac = (tid & 3) << 2;
    int br = tid >> 5, bc = (tid & 31) << 2;

    for (int k0 = 0; k0 < 256; k0 += 16) {
        #pragma unroll
        for (int i = 0; i < 2; i++) {
            int r = ar + 64 * i;
            const float4 v = *(const float4*)(Ab + (size_t)r * 256 + k0 + ac);
            As[ac + 0][r] = v.x; As[ac + 1][r] = v.y;
            As[ac + 2][r] = v.z; As[ac + 3][r] = v.w;
        }
        #pragma unroll
        for (int i = 0; i < 2; i++)
            *(float4*)&Bs[br + 8 * i][bc] =
                *(const float4*)(W1 + (size_t)(k0 + br + 8 * i) * 128 + bc);
        __syncthreads();
        #pragma unroll
        for (int kk = 0; kk < 16; kk++) {
            float a[8], b[8];
            *(float4*)(a)     = *(const float4*)&As[kk][ty * 8];
            *(float4*)(a + 4) = *(const float4*)&As[kk][ty * 8 + 4];
            *(float4*)(b)     = *(const float4*)&Bs[kk][tx * 8];
            *(float4*)(b + 4) = *(const float4*)&Bs[kk][tx * 8 + 4];
            #pragma unroll
            for (int i = 0; i < 8; i++)
                #pragma unroll
                for (int j = 0; j < 8; j++)
                    acc[i][j] = fmaf(a[i], b[j], acc[i][j]);
        }
        __syncthreads();
    }

    // epilogue: tanh, dot with W2, reduce across tx
    float part[8];
    #pragma unroll
    for (int i = 0; i < 8; i++) {
        part[i] = 0.f;
        #pragma unroll
        for (int j = 0; j < 8; j++) {
            int col = tx * 8 + j;
            float h = acc[i][j] + b1[col];
            part[i] += tanhf(h) * W2[col];
        }
    }
    #pragma unroll
    for (int i = 0; i < 8; i++) psum[ty * 8 + i][tx] = part[i];
    __syncthreads();
    if (tid < 128) {
        float s = 0.f;
        #pragma unroll
        for (int t = 0; t < 16; t++) s += psum[tid][t];
        s_out[(size_t)blockIdx.x * 128 + tid] = s + b2v[0];
    }
}

// ---------------- per-graph softmax + pools (1 block / graph) ----------------
__global__ __launch_bounds__(256)
void pool_kernel(const float* __restrict__ x, const float* __restrict__ s,
                 float* __restrict__ pooled)
{
    __shared__ float red[256];
    __shared__ float w_sm[256];
    int g = blockIdx.x;
    int beg = g_start[g], end = g_start[g + 1];
    if (beg < 0) beg = 0;
    if (end > N_NODES) end = N_NODES;
    int cnt = end - beg;
    int tid = threadIdx.x;

    // segment max of s
    float m = -3.402823466e38f;
    for (int i = beg + tid; i < end; i += 256) m = fmaxf(m, s[i]);
    red[tid] = m; __syncthreads();
    for (int off = 128; off > 0; off >>= 1) {
        if (tid < off) red[tid] = fmaxf(red[tid], red[tid + off]);
        __syncthreads();
    }
    float smax = red[0];
    __syncthreads();

    // segment sum of exp
    float e = 0.f;
    for (int i = beg + tid; i < end; i += 256) e += expf(s[i] - smax);
    red[tid] = e; __syncthreads();
    for (int off = 128; off > 0; off >>= 1) {
        if (tid < off) red[tid] += red[tid + off];
        __syncthreads();
    }
    float inv_den = (cnt > 0) ? (1.f / red[0]) : 0.f;
    __syncthreads();

    // pools: thread tid = channel
    float accw = 0.f, accs = 0.f, accm = -3.402823466e38f;
    for (int c0 = beg; c0 < end; c0 += 256) {
        int clen = min(256, end - c0);
        if (tid < clen) w_sm[tid] = expf(s[c0 + tid] - smax) * inv_den;
        __syncthreads();
        #pragma unroll 4
        for (int j = 0; j < clen; j++) {
            float xv = x[(size_t)(c0 + j) * 256 + tid];
            accw = fmaf(w_sm[j], xv, accw);
            accs += xv;
            accm = fmaxf(accm, xv);
        }
        __syncthreads();
    }
    float inv_c = (cnt > 0) ? (1.f / (float)cnt) : 0.f;
    size_t base = (size_t)g * 768;
    pooled[base + tid]       = accs * inv_c;             // mean
    pooled[base + 256 + tid] = (cnt > 0) ? accm : 0.f;   // max (zeroed if empty)
    pooled[base + 512 + tid] = (cnt > 0) ? accw : 0.f;   // weighted
}

// ---------------- generic SGEMM (128x128 tile, BK=16, 8x8/thread) ----------------
template<bool GELU, bool HASBIAS>
__global__ __launch_bounds__(256)
void sgemm_k(const float* __restrict__ A, const float* __restrict__ B,
             const float* __restrict__ bias, float* __restrict__ C,
             int K, int lda, int ldb, int ldc)
{
    __shared__ float As[16][132];
    __shared__ float Bs[16][128];

    int tid = threadIdx.x;
    int tx = tid & 15, ty = tid >> 4;
    const float* Ab = A + (size_t)blockIdx.x * 128 * lda;
    const float* Bb = B + (size_t)blockIdx.y * 128;

    float acc[8][8];
    #pragma unroll
    for (int i = 0; i < 8; i++)
        #pragma unroll
        for (int j = 0; j < 8; j++) acc[i][j] = 0.f;

    int ar = tid >> 2, ac = (tid & 3) << 2;
    int br = tid >> 5, bc = (tid & 31) << 2;

    for (int k0 = 0; k0 < K; k0 += 16) {
        #pragma unroll
        for (int i = 0; i < 2; i++) {
            int r = ar + 64 * i;
            const float4 v = *(const float4*)(Ab + (size_t)r * lda + k0 + ac);
            As[ac + 0][r] = v.x; As[ac + 1][r] = v.y;
            As[ac + 2][r] = v.z; As[ac + 3][r] = v.w;
        }
        #pragma unroll
        for (int i = 0; i < 2; i++)
            *(float4*)&Bs[br + 8 * i][bc] =
                *(const float4*)(Bb + (size_t)(k0 + br + 8 * i) * ldb + bc);
        __syncthreads();
        #pragma unroll
        for (int kk = 0; kk < 16; kk++) {
            float a[8], b[8];
            *(float4*)(a)     = *(const float4*)&As[kk][ty * 8];
            *(float4*)(a + 4) = *(const float4*)&As[kk][ty * 8 + 4];
            *(float4*)(b)     = *(const float4*)&Bs[kk][tx * 8];
            *(float4*)(b + 4) = *(const float4*)&Bs[kk][tx * 8 + 4];
            #pragma unroll
            for (int i = 0; i < 8; i++)
                #pragma unroll
                for (int j = 0; j < 8; j++)
                    acc[i][j] = fmaf(a[i], b[j], acc[i][j]);
        }
        __syncthreads();
    }

    int rb = blockIdx.x * 128 + ty * 8;
    int cb = blockIdx.y * 128 + tx * 8;
    #pragma unroll
    for (int i = 0; i < 8; i++) {
        float vals[8];
        #pragma unroll
        for (int j = 0; j < 8; j++) {
            float v = acc[i][j];
            if (HASBIAS) v += bias[cb + j];
            if (GELU)    v = 0.5f * v * (1.f + erff(v * 0.70710678118654752f));
            vals[j] = v;
        }
        *(float4*)(C + (size_t)(rb + i) * ldc + cb)     = *(float4*)(vals);
        *(float4*)(C + (size_t)(rb + i) * ldc + cb + 4) = *(float4*)(vals + 4);
    }
}

// ---------------- fused bias: bf = [bm,bx,bw]@Wc1 + bc1 ----------------
__global__ void bf_kernel(const float* __restrict__ bm, const float* __restrict__ bx,
                          const float* __restrict__ bw, const float* __restrict__ Wc1,
                          const float* __restrict__ bc1)
{
    int c = threadIdx.x;  // 512
    float acc = bc1[c];
    for (int j = 0; j < 256; j++) {
        acc = fmaf(bm[j], Wc1[(size_t)j * 512 + c], acc);
        acc = fmaf(bx[j], Wc1[(size_t)(256 + j) * 512 + c], acc);
        acc = fmaf(bw[j], Wc1[(size_t)(512 + j) * 512 + c], acc);
    }
    g_bf[c] = acc;
}

// ---------------- final GEMM [G,512]@[512,256] + bias + LayerNorm ----------------
#define GT 16
__global__ __launch_bounds__(256)
void out_kernel(const float* __restrict__ hid, const float* __restrict__ Wc2,
                const float* __restrict__ bc2, const float* __restrict__ gamma,
                const float* __restrict__ beta, float* __restrict__ out)
{
    __shared__ float hs[GT * 512];   // reused as [GT][256] output stage
    __shared__ float mu_s[GT], rs_s[GT];
    int gbase = blockIdx.x * GT;
    int o = threadIdx.x;             // output channel

    const float4* src = (const float4*)(hid + (size_t)gbase * 512);
    float4* dst4 = (float4*)hs;
    for (int i = o; i < GT * 512 / 4; i += 256) dst4[i] = src[i];
    __syncthreads();

    float acc[GT];
    #pragma unroll
    for (int gi = 0; gi < GT; gi++) acc[gi] = 0.f;

    #pragma unroll 2
    for (int k = 0; k < 512; k += 4) {
        float w0 = Wc2[(size_t)(k + 0) * 256 + o];
        float w1 = Wc2[(size_t)(k + 1) * 256 + o];
        float w2 = Wc2[(size_t)(k + 2) * 256 + o];
        float w3 = Wc2[(size_t)(k + 3) * 256 + o];
        #pragma unroll
        for (int gi = 0; gi < GT; gi++) {
            float4 h4 = *(const float4*)&hs[gi * 512 + k];
            acc[gi] = fmaf(h4.x, w0, acc[gi]);
            acc[gi] = fmaf(h4.y, w1, acc[gi]);
            acc[gi] = fmaf(h4.z, w2, acc[gi]);
            acc[gi] = fmaf(h4.w, w3, acc[gi]);
        }
    }
    __syncthreads();   // done reading hs

    float b = bc2[o];
    #pragma unroll
    for (int gi = 0; gi < GT; gi++) hs[gi * 256 + o] = acc[gi] + b;
    __syncthreads();

    int wid = o >> 5, lane = o & 31;
    #pragma unroll
    for (int q = 0; q < 2; q++) {
        int gi = wid * 2 + q;
        float sum = 0.f, sq = 0.f;
        for (int c = lane; c < 256; c += 32) {
            float v = hs[gi * 256 + c];
            sum += v; sq += v * v;
        }
        #pragma unroll
        for (int off = 16; off; off >>= 1) {
            sum += __shfl_xor_sync(0xffffffffu, sum, off);
            sq  += __shfl_xor_sync(0xffffffffu, sq, off);
        }
        if (lane == 0) {
            float mu  = sum * (1.f / 256.f);
            float var = sq * (1.f / 256.f) - mu * mu;
            mu_s[gi] = mu;
            rs_s[gi] = rsqrtf(var + 1e-5f);
        }
    }
    __syncthreads();

    float gm = gamma[o], bt = beta[o];
    #pragma unroll
    for (int gi = 0; gi < GT; gi++)
        out[(size_t)(gbase + gi) * 256 + o] =
            (hs[gi * 256 + o] - mu_s[gi]) * rs_s[gi] * gm + bt;
}

// ---------------- launcher ----------------
extern "C" void kernel_launch(void* const* d_in, const int* in_sizes, int n_in,
                              void* d_out, int out_size)
{
    const float* x      = (const float*)d_in[0];
    const int*   batch  = (const int*)d_in[1];     // jax default: int64 coerced to int32
    const float* W_att1 = (const float*)d_in[2];
    const float* b_att1 = (const float*)d_in[3];
    const float* W_att2 = (const float*)d_in[4];
    const float* b_att2 = (const float*)d_in[5];
    const float* Wm     = (const float*)d_in[6];
    const float* bm     = (const float*)d_in[7];
    const float* Wx     = (const float*)d_in[8];
    const float* bx     = (const float*)d_in[9];
    const float* Ww     = (const float*)d_in[10];
    const float* bw     = (const float*)d_in[11];
    const float* Wc1    = (const float*)d_in[12];
    const float* bc1    = (const float*)d_in[13];
    const float* Wc2    = (const float*)d_in[14];
    const float* bc2    = (const float*)d_in[15];
    const float* gamma  = (const float*)d_in[16];
    const float* beta   = (const float*)d_in[17];
    float*       out    = (float*)d_out;

    float *d_s, *d_pooled, *d_Wf, *d_bf, *d_hid;
    cudaGetSymbolAddress((void**)&d_s,      g_s);
    cudaGetSymbolAddress((void**)&d_pooled, g_pooled);
    cudaGetSymbolAddress((void**)&d_Wf,     g_Wf);
    cudaGetSymbolAddress((void**)&d_bf,     g_bf);
    cudaGetSymbolAddress((void**)&d_hid,    g_hid);

    // 1. segment starts
    seg_start_kernel<<<N_NODES / 256, 256>>>(batch);

    // 2. fused tail weights: Wf = blockdiag(Wm,Wx,Ww) @ Wc1, bf = [bm,bx,bw]@Wc1 + bc1
    sgemm_k<false, false><<<dim3(2, 4), 256>>>(Wm, Wc1,             nullptr, d_Wf,             256, 256, 512, 512);
    sgemm_k<false, false><<<dim3(2, 4), 256>>>(Wx, Wc1 + 256 * 512, nullptr, d_Wf + 256 * 512, 256, 256, 512, 512);
    sgemm_k<false, false><<<dim3(2, 4), 256>>>(Ww, Wc1 + 512 * 512, nullptr, d_Wf + 512 * 512, 256, 256, 512, 512);
    bf_kernel<<<1, 512>>>(bm, bx, bw, Wc1, bc1);

    // 3. node attention scores
    score_kernel<<<N_NODES / 128, 256>>>(x, W_att1, b_att1, W_att2, b_att2, d_s);

    // 4. per-graph softmax + pools
    pool_kernel<<<NUM_GRAPHS, 256>>>(x, d_s, d_pooled);

    // 5. hid = gelu(pooled @ Wf + bf)
    sgemm_k<true, true><<<dim3(NUM_GRAPHS / 128, 4), 256>>>(d_pooled, d_Wf, d_bf, d_hid, 768, 768, 512, 512);

    // 6. out = LN(hid @ Wc2 + bc2) * gamma + beta
    out_kernel<<<NUM_GRAPHS / GT, 256>>>(d_hid, Wc2, bc2, gamma, beta, out);
}

// round 4
// speedup vs baseline: 1.9336x; 1.9336x over previous
#include <cuda_runtime.h>
#include <cuda_bf16.h>
#include <math.h>
#include <stdint.h>

#define N_NODES    524288
#define NUM_GRAPHS 8192
#define HDIM       256

// ---------------- scratch (static device globals; no allocation) ----------------
__device__ float g_s[N_NODES];                    // per-node attention score
__device__ int   g_start[NUM_GRAPHS + 1];         // segment starts
__device__ float g_pooled[NUM_GRAPHS * 768];      // [mean | max | weighted]
__device__ float g_Wf[768 * 512];                 // fused blockdiag(Wm,Wx,Ww)@Wc1
__device__ float g_bf[512];                       // fused bias
__device__ float g_hid[NUM_GRAPHS * 512];         // gelu hidden

// ---------------- helpers ----------------
__device__ __forceinline__ uint32_t f2tf32(float f) {
    uint32_t u;
    asm("cvt.rna.tf32.f32 %0, %1;" : "=r"(u) : "f"(f));
    return u;
}

__device__ __forceinline__ void mma_tf32(float c[4],
    uint32_t a0, uint32_t a1, uint32_t a2, uint32_t a3,
    uint32_t b0, uint32_t b1)
{
    asm volatile(
        "mma.sync.aligned.m16n8k8.row.col.f32.tf32.tf32.f32 "
        "{%0,%1,%2,%3}, {%4,%5,%6,%7}, {%8,%9}, {%0,%1,%2,%3};"
        : "+f"(c[0]), "+f"(c[1]), "+f"(c[2]), "+f"(c[3])
        : "r"(a0), "r"(a1), "r"(a2), "r"(a3), "r"(b0), "r"(b1));
}

// ---------------- segment starts from sorted batch (int32) ----------------
__global__ void seg_start_kernel(const int* __restrict__ batch) {
    int n = blockIdx.x * blockDim.x + threadIdx.x;
    if (n >= N_NODES) return;
    int b  = batch[n];
    int pb = (n == 0) ? -1 : batch[n - 1];
    if (b >= NUM_GRAPHS) b = NUM_GRAPHS - 1;
    if (pb < -1) pb = -1;
    if (pb > b)  pb = b;
    for (int g = pb + 1; g <= b; g++) g_start[g] = n;
    if (n == N_NODES - 1)
        for (int g = b + 1; g <= NUM_GRAPHS; g++) g_start[g] = N_NODES;
}

// ============================================================================
// score: s = tanh(x@W1 + b1) @ W2 + b2 using tf32 mma.
// Block: 128 rows x 128 cols (full hidden), K=256.
// 8 warps in 2x4 grid: warp tile 64m x 32n -> 4 mfrag x 4 nfrag of m16n8k8.
// ============================================================================
__global__ __launch_bounds__(256)
void score_mma(const float* __restrict__ x, const float* __restrict__ W1,
               const float* __restrict__ b1, const float* __restrict__ W2,
               const float* __restrict__ b2v, float* __restrict__ s_out)
{
    __shared__ uint32_t As[128][36];   // [m][k] stride 36 -> conflict-free frag reads
    __shared__ uint32_t Bs[32][136];   // [k][n] stride 136 -> conflict-free frag reads
    __shared__ float    psum[128][5];

    const int tid  = threadIdx.x;
    const int lane = tid & 31, warp = tid >> 5;
    const int wy = warp >> 2, wx = warp & 3;
    const int g = lane >> 2, t = lane & 3;

    const float* Ab = x + (size_t)blockIdx.x * 128 * 256;

    float c[4][4][4];
    #pragma unroll
    for (int mf = 0; mf < 4; mf++)
        #pragma unroll
        for (int nf = 0; nf < 4; nf++)
            #pragma unroll
            for (int r = 0; r < 4; r++) c[mf][nf][r] = 0.f;

    for (int k0 = 0; k0 < 256; k0 += 32) {
        // stage A tile 128x32 (tf32)
        #pragma unroll
        for (int i = 0; i < 4; i++) {
            int fid = tid + i * 256;
            int row = fid >> 3, c4 = (fid & 7) << 2;
            float4 v = *(const float4*)(Ab + (size_t)row * 256 + k0 + c4);
            uint32_t u[4] = { f2tf32(v.x), f2tf32(v.y), f2tf32(v.z), f2tf32(v.w) };
            *(uint4*)&As[row][c4] = *(uint4*)u;
        }
        // stage B tile 32x128 (tf32)
        #pragma unroll
        for (int i = 0; i < 4; i++) {
            int fid = tid + i * 256;
            int row = fid >> 5, c4 = (fid & 31) << 2;
            float4 v = *(const float4*)(W1 + (size_t)(k0 + row) * 128 + c4);
            uint32_t u[4] = { f2tf32(v.x), f2tf32(v.y), f2tf32(v.z), f2tf32(v.w) };
            *(uint4*)&Bs[row][c4] = *(uint4*)u;
        }
        __syncthreads();

        #pragma unroll
        for (int kk = 0; kk < 32; kk += 8) {
            uint32_t a[4][4], b[4][2];
            #pragma unroll
            for (int mf = 0; mf < 4; mf++) {
                int row = wy * 64 + mf * 16 + g;
                a[mf][0] = As[row][kk + t];
                a[mf][1] = As[row + 8][kk + t];
                a[mf][2] = As[row][kk + t + 4];
                a[mf][3] = As[row + 8][kk + t + 4];
            }
            #pragma unroll
            for (int nf = 0; nf < 4; nf++) {
                int col = wx * 32 + nf * 8 + g;
                b[nf][0] = Bs[kk + t][col];
                b[nf][1] = Bs[kk + t + 4][col];
            }
            #pragma unroll
            for (int mf = 0; mf < 4; mf++)
                #pragma unroll
                for (int nf = 0; nf < 4; nf++)
                    mma_tf32(c[mf][nf], a[mf][0], a[mf][1], a[mf][2], a[mf][3],
                             b[nf][0], b[nf][1]);
        }
        __syncthreads();
    }

    // epilogue: tanh(acc + b1) * W2, reduce over the 128 hidden cols
    #pragma unroll
    for (int mf = 0; mf < 4; mf++) {
        #pragma unroll
        for (int h = 0; h < 2; h++) {
            float p = 0.f;
            #pragma unroll
            for (int nf = 0; nf < 4; nf++) {
                #pragma unroll
                for (int e = 0; e < 2; e++) {
                    int col = wx * 32 + nf * 8 + 2 * t + e;
                    float v = c[mf][nf][h * 2 + e] + __ldg(&b1[col]);
                    p += tanhf(v) * __ldg(&W2[col]);
                }
            }
            // reduce across the 4 lanes sharing this row (lane bits 0-1)
            p += __shfl_xor_sync(0xffffffffu, p, 1);
            p += __shfl_xor_sync(0xffffffffu, p, 2);
            if (t == 0) psum[wy * 64 + mf * 16 + g + 8 * h][wx] = p;
        }
    }
    __syncthreads();
    if (tid < 128) {
        float s = psum[tid][0] + psum[tid][1] + psum[tid][2] + psum[tid][3];
        s_out[(size_t)blockIdx.x * 128 + tid] = s + b2v[0];
    }
}

// ============================================================================
// generic tf32 GEMM: C[M,N] = A[M,K] @ B[K,N] (+bias, +gelu)
// Block 128x128, K chunked by 32. Same warp layout as score_mma.
// ============================================================================
template<bool GELU, bool HASBIAS>
__global__ __launch_bounds__(256)
void gemm_tf32(const float* __restrict__ A, const float* __restrict__ B,
               const float* __restrict__ bias, float* __restrict__ C,
               int K, int lda, int ldb, int ldc)
{
    __shared__ uint32_t As[128][36];
    __shared__ uint32_t Bs[32][136];

    const int tid  = threadIdx.x;
    const int lane = tid & 31, warp = tid >> 5;
    const int wy = warp >> 2, wx = warp & 3;
    const int g = lane >> 2, t = lane & 3;

    const float* Ab = A + (size_t)blockIdx.x * 128 * lda;
    const float* Bb = B + (size_t)blockIdx.y * 128;

    float c[4][4][4];
    #pragma unroll
    for (int mf = 0; mf < 4; mf++)
        #pragma unroll
        for (int nf = 0; nf < 4; nf++)
            #pragma unroll
            for (int r = 0; r < 4; r++) c[mf][nf][r] = 0.f;

    for (int k0 = 0; k0 < K; k0 += 32) {
        #pragma unroll
        for (int i = 0; i < 4; i++) {
            int fid = tid + i * 256;
            int row = fid >> 3, c4 = (fid & 7) << 2;
            float4 v = *(const float4*)(Ab + (size_t)row * lda + k0 + c4);
            uint32_t u[4] = { f2tf32(v.x), f2tf32(v.y), f2tf32(v.z), f2tf32(v.w) };
            *(uint4*)&As[row][c4] = *(uint4*)u;
        }
        #pragma unroll
        for (int i = 0; i < 4; i++) {
            int fid = tid + i * 256;
            int row = fid >> 5, c4 = (fid & 31) << 2;
            float4 v = *(const float4*)(Bb + (size_t)(k0 + row) * ldb + c4);
            uint32_t u[4] = { f2tf32(v.x), f2tf32(v.y), f2tf32(v.z), f2tf32(v.w) };
            *(uint4*)&Bs[row][c4] = *(uint4*)u;
        }
        __syncthreads();

        #pragma unroll
        for (int kk = 0; kk < 32; kk += 8) {
            uint32_t a[4][4], b[4][2];
            #pragma unroll
            for (int mf = 0; mf < 4; mf++) {
                int row = wy * 64 + mf * 16 + g;
                a[mf][0] = As[row][kk + t];
                a[mf][1] = As[row + 8][kk + t];
                a[mf][2] = As[row][kk + t + 4];
                a[mf][3] = As[row + 8][kk + t + 4];
            }
            #pragma unroll
            for (int nf = 0; nf < 4; nf++) {
                int col = wx * 32 + nf * 8 + g;
                b[nf][0] = Bs[kk + t][col];
                b[nf][1] = Bs[kk + t + 4][col];
            }
            #pragma unroll
            for (int mf = 0; mf < 4; mf++)
                #pragma unroll
                for (int nf = 0; nf < 4; nf++)
                    mma_tf32(c[mf][nf], a[mf][0], a[mf][1], a[mf][2], a[mf][3],
                             b[nf][0], b[nf][1]);
        }
        __syncthreads();
    }

    // epilogue: per-thread 16 float2 stores
    #pragma unroll
    for (int mf = 0; mf < 4; mf++) {
        #pragma unroll
        for (int h = 0; h < 2; h++) {
            int row = blockIdx.x * 128 + wy * 64 + mf * 16 + g + 8 * h;
            #pragma unroll
            for (int nf = 0; nf < 4; nf++) {
                int col = blockIdx.y * 128 + wx * 32 + nf * 8 + 2 * t;
                float v0 = c[mf][nf][h * 2 + 0];
                float v1 = c[mf][nf][h * 2 + 1];
                if (HASBIAS) { v0 += __ldg(&bias[col]); v1 += __ldg(&bias[col + 1]); }
                if (GELU) {
                    v0 = 0.5f * v0 * (1.f + erff(v0 * 0.70710678118654752f));
                    v1 = 0.5f * v1 * (1.f + erff(v1 * 0.70710678118654752f));
                }
                float2 st = { v0, v1 };
                *(float2*)(C + (size_t)row * ldc + col) = st;
            }
        }
    }
}

// ============================================================================
// fused weight prep (fp32 for precision): Wf[z] = W(z)[256,256] @ Wc1[z][256,512]
// 64x64 tiles, grid (4, 8, 3)
// ============================================================================
__global__ __launch_bounds__(256)
void wf_kernel(const float* __restrict__ Wm, const float* __restrict__ Wx,
               const float* __restrict__ Ww, const float* __restrict__ Wc1,
               float* __restrict__ Wf)
{
    __shared__ float As[16][68];
    __shared__ float Bs[16][68];

    int z = blockIdx.z;
    const float* A = (z == 0) ? Wm : (z == 1) ? Wx : Ww;
    const float* B = Wc1 + (size_t)z * 256 * 512;
    float*       C = Wf  + (size_t)z * 256 * 512;

    int tid = threadIdx.x;
    int tx = tid & 15, ty = tid >> 4;
    int ar = tid >> 2, ac = (tid & 3) << 2;
    int br = tid >> 4, bc = (tid & 15) << 2;

    float acc[4][4];
    #pragma unroll
    for (int i = 0; i < 4; i++)
        #pragma unroll
        for (int j = 0; j < 4; j++) acc[i][j] = 0.f;

    for (int k0 = 0; k0 < 256; k0 += 16) {
        float4 va = *(const float4*)(A + (size_t)(blockIdx.x * 64 + ar) * 256 + k0 + ac);
        As[ac + 0][ar] = va.x; As[ac + 1][ar] = va.y;
        As[ac + 2][ar] = va.z; As[ac + 3][ar] = va.w;
        float4 vb = *(const float4*)(B + (size_t)(k0 + br) * 512 + blockIdx.y * 64 + bc);
        *(float4*)&Bs[br][bc] = vb;
        __syncthreads();
        #pragma unroll
        for (int kk = 0; kk < 16; kk++) {
            float a[4], b[4];
            #pragma unroll
            for (int i = 0; i < 4; i++) a[i] = As[kk][ty * 4 + i];
            #pragma unroll
            for (int j = 0; j < 4; j++) b[j] = Bs[kk][tx * 4 + j];
            #pragma unroll
            for (int i = 0; i < 4; i++)
                #pragma unroll
                for (int j = 0; j < 4; j++)
                    acc[i][j] = fmaf(a[i], b[j], acc[i][j]);
        }
        __syncthreads();
    }
    #pragma unroll
    for (int i = 0; i < 4; i++)
        *(float4*)(C + (size_t)(blockIdx.x * 64 + ty * 4 + i) * 512 + blockIdx.y * 64 + tx * 4) =
            *(float4*)acc[i];
}

// ---------------- per-graph softmax + pools (1 block / graph) ----------------
__global__ __launch_bounds__(256)
void pool_kernel(const float* __restrict__ x, const float* __restrict__ s,
                 float* __restrict__ pooled)
{
    __shared__ float red[256];
    __shared__ float w_sm[256];
    int g = blockIdx.x;
    int beg = g_start[g], end = g_start[g + 1];
    if (beg < 0) beg = 0;
    if (end > N_NODES) end = N_NODES;
    int cnt = end - beg;
    int tid = threadIdx.x;

    float m = -3.402823466e38f;
    for (int i = beg + tid; i < end; i += 256) m = fmaxf(m, s[i]);
    red[tid] = m; __syncthreads();
    for (int off = 128; off > 0; off >>= 1) {
        if (tid < off) red[tid] = fmaxf(red[tid], red[tid + off]);
        __syncthreads();
    }
    float smax = red[0];
    __syncthreads();

    float e = 0.f;
    for (int i = beg + tid; i < end; i += 256) e += expf(s[i] - smax);
    red[tid] = e; __syncthreads();
    for (int off = 128; off > 0; off >>= 1) {
        if (tid < off) red[tid] += red[tid + off];
        __syncthreads();
    }
    float inv_den = (cnt > 0) ? (1.f / red[0]) : 0.f;
    __syncthreads();

    float accw = 0.f, accs = 0.f, accm = -3.402823466e38f;
    for (int c0 = beg; c0 < end; c0 += 256) {
        int clen = min(256, end - c0);
        if (tid < clen) w_sm[tid] = expf(s[c0 + tid] - smax) * inv_den;
        __syncthreads();
        #pragma unroll 4
        for (int j = 0; j < clen; j++) {
            float xv = x[(size_t)(c0 + j) * 256 + tid];
            accw = fmaf(w_sm[j], xv, accw);
            accs += xv;
            accm = fmaxf(accm, xv);
        }
        __syncthreads();
    }
    float inv_c = (cnt > 0) ? (1.f / (float)cnt) : 0.f;
    size_t base = (size_t)g * 768;
    pooled[base + tid]       = accs * inv_c;
    pooled[base + 256 + tid] = (cnt > 0) ? accm : 0.f;
    pooled[base + 512 + tid] = (cnt > 0) ? accw : 0.f;
}

// ---------------- fused bias: bf = [bm,bx,bw]@Wc1 + bc1 ----------------
__global__ void bf_kernel(const float* __restrict__ bm, const float* __restrict__ bx,
                          const float* __restrict__ bw, const float* __restrict__ Wc1,
                          const float* __restrict__ bc1)
{
    int c = threadIdx.x;  // 512
    float acc = bc1[c];
    for (int j = 0; j < 256; j++) {
        acc = fmaf(bm[j], Wc1[(size_t)j * 512 + c], acc);
        acc = fmaf(bx[j], Wc1[(size_t)(256 + j) * 512 + c], acc);
        acc = fmaf(bw[j], Wc1[(size_t)(512 + j) * 512 + c], acc);
    }
    g_bf[c] = acc;
}

// ---------------- final GEMM [G,512]@[512,256] + bias + LayerNorm ----------------
#define GT 16
__global__ __launch_bounds__(256)
void out_kernel(const float* __restrict__ hid, const float* __restrict__ Wc2,
                const float* __restrict__ bc2, const float* __restrict__ gamma,
                const float* __restrict__ beta, float* __restrict__ out)
{
    __shared__ float hs[GT * 512];
    __shared__ float mu_s[GT], rs_s[GT];
    int gbase = blockIdx.x * GT;
    int o = threadIdx.x;

    const float4* src = (const float4*)(hid + (size_t)gbase * 512);
    float4* dst4 = (float4*)hs;
    for (int i = o; i < GT * 512 / 4; i += 256) dst4[i] = src[i];
    __syncthreads();

    float acc[GT];
    #pragma unroll
    for (int gi = 0; gi < GT; gi++) acc[gi] = 0.f;

    #pragma unroll 2
    for (int k = 0; k < 512; k += 4) {
        float w0 = Wc2[(size_t)(k + 0) * 256 + o];
        float w1 = Wc2[(size_t)(k + 1) * 256 + o];
        float w2 = Wc2[(size_t)(k + 2) * 256 + o];
        float w3 = Wc2[(size_t)(k + 3) * 256 + o];
        #pragma unroll
        for (int gi = 0; gi < GT; gi++) {
            float4 h4 = *(const float4*)&hs[gi * 512 + k];
            acc[gi] = fmaf(h4.x, w0, acc[gi]);
            acc[gi] = fmaf(h4.y, w1, acc[gi]);
            acc[gi] = fmaf(h4.z, w2, acc[gi]);
            acc[gi] = fmaf(h4.w, w3, acc[gi]);
        }
    }
    __syncthreads();

    float b = bc2[o];
    #pragma unroll
    for (int gi = 0; gi < GT; gi++) hs[gi * 256 + o] = acc[gi] + b;
    __syncthreads();

    int wid = o >> 5, lane = o & 31;
    #pragma unroll
    for (int q = 0; q < 2; q++) {
        int gi = wid * 2 + q;
        float sum = 0.f, sq = 0.f;
        for (int c = lane; c < 256; c += 32) {
            float v = hs[gi * 256 + c];
            sum += v; sq += v * v;
        }
        #pragma unroll
        for (int off = 16; off; off >>= 1) {
            sum += __shfl_xor_sync(0xffffffffu, sum, off);
            sq  += __shfl_xor_sync(0xffffffffu, sq, off);
        }
        if (lane == 0) {
            float mu  = sum * (1.f / 256.f);
            float var = sq * (1.f / 256.f) - mu * mu;
            mu_s[gi] = mu;
            rs_s[gi] = rsqrtf(var + 1e-5f);
        }
    }
    __syncthreads();

    float gm = gamma[o], bt = beta[o];
    #pragma unroll
    for (int gi = 0; gi < GT; gi++)
        out[(size_t)(gbase + gi) * 256 + o] =
            (hs[gi * 256 + o] - mu_s[gi]) * rs_s[gi] * gm + bt;
}

// ---------------- launcher ----------------
extern "C" void kernel_launch(void* const* d_in, const int* in_sizes, int n_in,
                              void* d_out, int out_size)
{
    const float* x      = (const float*)d_in[0];
    const int*   batch  = (const int*)d_in[1];
    const float* W_att1 = (const float*)d_in[2];
    const float* b_att1 = (const float*)d_in[3];
    const float* W_att2 = (const float*)d_in[4];
    const float* b_att2 = (const float*)d_in[5];
    const float* Wm     = (const float*)d_in[6];
    const float* bm     = (const float*)d_in[7];
    const float* Wx     = (const float*)d_in[8];
    const float* bx     = (const float*)d_in[9];
    const float* Ww     = (const float*)d_in[10];
    const float* bw     = (const float*)d_in[11];
    const float* Wc1    = (const float*)d_in[12];
    const float* bc1    = (const float*)d_in[13];
    const float* Wc2    = (const float*)d_in[14];
    const float* bc2    = (const float*)d_in[15];
    const float* gamma  = (const float*)d_in[16];
    const float* beta   = (const float*)d_in[17];
    float*       out    = (float*)d_out;

    float *d_s, *d_pooled, *d_Wf, *d_bf, *d_hid;
    cudaGetSymbolAddress((void**)&d_s,      g_s);
    cudaGetSymbolAddress((void**)&d_pooled, g_pooled);
    cudaGetSymbolAddress((void**)&d_Wf,     g_Wf);
    cudaGetSymbolAddress((void**)&d_bf,     g_bf);
    cudaGetSymbolAddress((void**)&d_hid,    g_hid);

    // 1. segment starts
    seg_start_kernel<<<N_NODES / 256, 256>>>(batch);

    // 2. fused tail weights (fp32, one launch, 96 blocks)
    wf_kernel<<<dim3(4, 8, 3), 256>>>(Wm, Wx, Ww, Wc1, d_Wf);
    bf_kernel<<<1, 512>>>(bm, bx, bw, Wc1, bc1);

    // 3. node attention scores (tf32 tensor cores)
    score_mma<<<N_NODES / 128, 256>>>(x, W_att1, b_att1, W_att2, b_att2, d_s);

    // 4. per-graph softmax + pools
    pool_kernel<<<NUM_GRAPHS, 256>>>(x, d_s, d_pooled);

    // 5. hid = gelu(pooled @ Wf + bf)  (tf32 tensor cores)
    gemm_tf32<true, true><<<dim3(NUM_GRAPHS / 128, 4), 256>>>(d_pooled, d_Wf, d_bf, d_hid, 768, 768, 512, 512);

    // 6. out = LN(hid @ Wc2 + bc2) * gamma + beta
    out_kernel<<<NUM_GRAPHS / GT, 256>>>(d_hid, Wc2, bc2, gamma, beta, out);
}

// round 5
// speedup vs baseline: 2.2001x; 1.1378x over previous
#include <cuda_runtime.h>
#include <cuda_bf16.h>
#include <math.h>
#include <stdint.h>

#define N_NODES    524288
#define NUM_GRAPHS 8192
#define HDIM       256

// ---------------- scratch (static device globals; no allocation) ----------------
__device__ float g_s[N_NODES];                    // per-node attention score
__device__ int   g_start[NUM_GRAPHS + 1];         // segment starts
__device__ float g_pooled[NUM_GRAPHS * 768];      // [mean | max | weighted]
__device__ float g_Wf[768 * 512];                 // fused blockdiag(Wm,Wx,Ww)@Wc1
__device__ float g_bf[512];                       // fused bias
__device__ float g_hid[NUM_GRAPHS * 512];         // gelu hidden
__device__ float g_y[NUM_GRAPHS * 256];           // pre-LN output

// ---------------- helpers ----------------
__device__ __forceinline__ uint32_t f2tf32(float f) {
    uint32_t u;
    asm("cvt.rna.tf32.f32 %0, %1;" : "=r"(u) : "f"(f));
    return u;
}

__device__ __forceinline__ void mma_tf32(float c[4],
    uint32_t a0, uint32_t a1, uint32_t a2, uint32_t a3,
    uint32_t b0, uint32_t b1)
{
    asm volatile(
        "mma.sync.aligned.m16n8k8.row.col.f32.tf32.tf32.f32 "
        "{%0,%1,%2,%3}, {%4,%5,%6,%7}, {%8,%9}, {%0,%1,%2,%3};"
        : "+f"(c[0]), "+f"(c[1]), "+f"(c[2]), "+f"(c[3])
        : "r"(a0), "r"(a1), "r"(a2), "r"(a3), "r"(b0), "r"(b1));
}

// ---------------- segment starts from sorted batch (int32) ----------------
__global__ void seg_start_kernel(const int* __restrict__ batch) {
    int n = blockIdx.x * blockDim.x + threadIdx.x;
    if (n >= N_NODES) return;
    int b  = batch[n];
    int pb = (n == 0) ? -1 : batch[n - 1];
    if (b >= NUM_GRAPHS) b = NUM_GRAPHS - 1;
    if (pb < -1) pb = -1;
    if (pb > b)  pb = b;
    for (int g = pb + 1; g <= b; g++) g_start[g] = n;
    if (n == N_NODES - 1)
        for (int g = b + 1; g <= NUM_GRAPHS; g++) g_start[g] = N_NODES;
}

// ============================================================================
// score v2: s = tanh(x@W1 + b1) @ W2 + b2
// Block tile 256m x 128n, 8 warps (4x2) with 64x64 warp tiles (mf=4, nf=8).
// A staged via cp.async double-buffer (raw fp32 -> tf32 truncate),
// B register-staged with cvt.rna. One syncthreads per K-chunk of 32.
// ============================================================================
#define SC_AS_WORDS (2 * 256 * 36)
#define SC_BS_WORDS (2 * 32 * 136)
#define SC_SMEM_BYTES ((SC_AS_WORDS + SC_BS_WORDS + 512 + 32) * 4)

__global__ __launch_bounds__(256)
void score_mma_v2(const float* __restrict__ x, const float* __restrict__ W1,
                  const float* __restrict__ b1, const float* __restrict__ W2,
                  const float* __restrict__ b2v, float* __restrict__ s_out)
{
    extern __shared__ uint32_t sm[];
    uint32_t* AsW = sm;                                  // [2][256][36]
    uint32_t* BsW = sm + SC_AS_WORDS;                    // [2][32][136]
    float*   psum = (float*)(sm + SC_AS_WORDS + SC_BS_WORDS);  // [256][2]

    const int tid  = threadIdx.x;
    const int lane = tid & 31, warp = tid >> 5;
    const int wy = warp >> 1, wx = warp & 1;             // 4 x 2 warps
    const int g = lane >> 2, t = lane & 3;

    const float* Ab = x + (size_t)blockIdx.x * 256 * 256;

    const uint32_t As_sh = (uint32_t)__cvta_generic_to_shared(AsW);

    float c[4][8][4];
    #pragma unroll
    for (int mf = 0; mf < 4; mf++)
        #pragma unroll
        for (int nf = 0; nf < 8; nf++)
            #pragma unroll
            for (int r = 0; r < 4; r++) c[mf][nf][r] = 0.f;

    float4 breg[4];

    auto cpaA = [&](int ch) {
        const int buf = ch & 1;
        #pragma unroll
        for (int i = 0; i < 8; i++) {
            int fid = tid + i * 256;
            int row = fid >> 3, c4 = (fid & 7) << 2;
            const float* gp = Ab + (size_t)row * 256 + ch * 32 + c4;
            uint32_t sp = As_sh + (uint32_t)(((buf * 256 + row) * 36 + c4) * 4);
            asm volatile("cp.async.cg.shared.global [%0], [%1], 16;\n"
                         :: "r"(sp), "l"(gp));
        }
        asm volatile("cp.async.commit_group;\n" ::);
    };
    auto ldgB = [&](int ch) {
        #pragma unroll
        for (int i = 0; i < 4; i++) {
            int fid = tid + i * 256;
            int row = fid >> 5, c4 = (fid & 31) << 2;
            breg[i] = *(const float4*)(W1 + (size_t)(ch * 32 + row) * 128 + c4);
        }
    };
    auto stsB = [&](int ch) {
        const int buf = ch & 1;
        #pragma unroll
        for (int i = 0; i < 4; i++) {
            int fid = tid + i * 256;
            int row = fid >> 5, c4 = (fid & 31) << 2;
            uint32_t u[4] = { f2tf32(breg[i].x), f2tf32(breg[i].y),
                              f2tf32(breg[i].z), f2tf32(breg[i].w) };
            *(uint4*)&BsW[(buf * 32 + row) * 136 + c4] = *(uint4*)u;
        }
    };

    cpaA(0);
    ldgB(0);
    stsB(0);
    ldgB(1);

    for (int ch = 0; ch < 8; ch++) {
        asm volatile("cp.async.wait_group 0;\n" ::);
        __syncthreads();
        if (ch < 7) {
            cpaA(ch + 1);
            stsB(ch + 1);
            if (ch < 6) ldgB(ch + 2);
        }
        const int buf = ch & 1;
        const uint32_t* A_s = AsW + buf * 256 * 36;
        const uint32_t* B_s = BsW + buf * 32 * 136;

        #pragma unroll
        for (int kk = 0; kk < 32; kk += 8) {
            uint32_t a[4][4], b[8][2];
            #pragma unroll
            for (int mf = 0; mf < 4; mf++) {
                int row = wy * 64 + mf * 16 + g;
                a[mf][0] = A_s[row * 36 + kk + t];
                a[mf][1] = A_s[(row + 8) * 36 + kk + t];
                a[mf][2] = A_s[row * 36 + kk + t + 4];
                a[mf][3] = A_s[(row + 8) * 36 + kk + t + 4];
            }
            #pragma unroll
            for (int nf = 0; nf < 8; nf++) {
                int col = wx * 64 + nf * 8 + g;
                b[nf][0] = B_s[(kk + t) * 136 + col];
                b[nf][1] = B_s[(kk + t + 4) * 136 + col];
            }
            #pragma unroll
            for (int mf = 0; mf < 4; mf++)
                #pragma unroll
                for (int nf = 0; nf < 8; nf++)
                    mma_tf32(c[mf][nf], a[mf][0], a[mf][1], a[mf][2], a[mf][3],
                             b[nf][0], b[nf][1]);
        }
    }

    // epilogue: tanh(acc + b1) * W2, reduce over 128 hidden cols
    #pragma unroll
    for (int mf = 0; mf < 4; mf++) {
        #pragma unroll
        for (int h = 0; h < 2; h++) {
            float p = 0.f;
            #pragma unroll
            for (int nf = 0; nf < 8; nf++) {
                #pragma unroll
                for (int e = 0; e < 2; e++) {
                    int col = wx * 64 + nf * 8 + 2 * t + e;
                    float v = c[mf][nf][h * 2 + e] + __ldg(&b1[col]);
                    p += tanhf(v) * __ldg(&W2[col]);
                }
            }
            p += __shfl_xor_sync(0xffffffffu, p, 1);
            p += __shfl_xor_sync(0xffffffffu, p, 2);
            if (t == 0) psum[(wy * 64 + mf * 16 + g + 8 * h) * 2 + wx] = p;
        }
    }
    __syncthreads();
    float s = psum[tid * 2] + psum[tid * 2 + 1] + b2v[0];
    s_out[(size_t)blockIdx.x * 256 + tid] = s;
}

// ============================================================================
// generic tf32 GEMM: C[M,N] = A[M,K] @ B[K,N] (+bias, +gelu)
// Block 128x128, K chunked by 32, 8 warps (2x4) with 64x32 warp tiles.
// ============================================================================
template<bool GELU, bool HASBIAS>
__global__ __launch_bounds__(256)
void gemm_tf32(const float* __restrict__ A, const float* __restrict__ B,
               const float* __restrict__ bias, float* __restrict__ C,
               int K, int lda, int ldb, int ldc)
{
    __shared__ uint32_t As[128][36];
    __shared__ uint32_t Bs[32][136];

    const int tid  = threadIdx.x;
    const int lane = tid & 31, warp = tid >> 5;
    const int wy = warp >> 2, wx = warp & 3;
    const int g = lane >> 2, t = lane & 3;

    const float* Ab = A + (size_t)blockIdx.x * 128 * lda;
    const float* Bb = B + (size_t)blockIdx.y * 128;

    float c[4][4][4];
    #pragma unroll
    for (int mf = 0; mf < 4; mf++)
        #pragma unroll
        for (int nf = 0; nf < 4; nf++)
            #pragma unroll
            for (int r = 0; r < 4; r++) c[mf][nf][r] = 0.f;

    for (int k0 = 0; k0 < K; k0 += 32) {
        #pragma unroll
        for (int i = 0; i < 4; i++) {
            int fid = tid + i * 256;
            int row = fid >> 3, c4 = (fid & 7) << 2;
            float4 v = *(const float4*)(Ab + (size_t)row * lda + k0 + c4);
            uint32_t u[4] = { f2tf32(v.x), f2tf32(v.y), f2tf32(v.z), f2tf32(v.w) };
            *(uint4*)&As[row][c4] = *(uint4*)u;
        }
        #pragma unroll
        for (int i = 0; i < 4; i++) {
            int fid = tid + i * 256;
            int row = fid >> 5, c4 = (fid & 31) << 2;
            float4 v = *(const float4*)(Bb + (size_t)(k0 + row) * ldb + c4);
            uint32_t u[4] = { f2tf32(v.x), f2tf32(v.y), f2tf32(v.z), f2tf32(v.w) };
            *(uint4*)&Bs[row][c4] = *(uint4*)u;
        }
        __syncthreads();

        #pragma unroll
        for (int kk = 0; kk < 32; kk += 8) {
            uint32_t a[4][4], b[4][2];
            #pragma unroll
            for (int mf = 0; mf < 4; mf++) {
                int row = wy * 64 + mf * 16 + g;
                a[mf][0] = As[row][kk + t];
                a[mf][1] = As[row + 8][kk + t];
                a[mf][2] = As[row][kk + t + 4];
                a[mf][3] = As[row + 8][kk + t + 4];
            }
            #pragma unroll
            for (int nf = 0; nf < 4; nf++) {
                int col = wx * 32 + nf * 8 + g;
                b[nf][0] = Bs[kk + t][col];
                b[nf][1] = Bs[kk + t + 4][col];
            }
            #pragma unroll
            for (int mf = 0; mf < 4; mf++)
                #pragma unroll
                for (int nf = 0; nf < 4; nf++)
                    mma_tf32(c[mf][nf], a[mf][0], a[mf][1], a[mf][2], a[mf][3],
                             b[nf][0], b[nf][1]);
        }
        __syncthreads();
    }

    #pragma unroll
    for (int mf = 0; mf < 4; mf++) {
        #pragma unroll
        for (int h = 0; h < 2; h++) {
            int row = blockIdx.x * 128 + wy * 64 + mf * 16 + g + 8 * h;
            #pragma unroll
            for (int nf = 0; nf < 4; nf++) {
                int col = blockIdx.y * 128 + wx * 32 + nf * 8 + 2 * t;
                float v0 = c[mf][nf][h * 2 + 0];
                float v1 = c[mf][nf][h * 2 + 1];
                if (HASBIAS) { v0 += __ldg(&bias[col]); v1 += __ldg(&bias[col + 1]); }
                if (GELU) {
                    v0 = 0.5f * v0 * (1.f + erff(v0 * 0.70710678118654752f));
                    v1 = 0.5f * v1 * (1.f + erff(v1 * 0.70710678118654752f));
                }
                float2 st = { v0, v1 };
                *(float2*)(C + (size_t)row * ldc + col) = st;
            }
        }
    }
}

// ============================================================================
// fused weight prep (fp32): Wf[z] = W(z)[256,256] @ Wc1[z*256:, 512]
// ============================================================================
__global__ __launch_bounds__(256)
void wf_kernel(const float* __restrict__ Wm, const float* __restrict__ Wx,
               const float* __restrict__ Ww, const float* __restrict__ Wc1,
               float* __restrict__ Wf)
{
    __shared__ float As[16][68];
    __shared__ float Bs[16][68];

    int z = blockIdx.z;
    const float* A = (z == 0) ? Wm : (z == 1) ? Wx : Ww;
    const float* B = Wc1 + (size_t)z * 256 * 512;
    float*       C = Wf  + (size_t)z * 256 * 512;

    int tid = threadIdx.x;
    int tx = tid & 15, ty = tid >> 4;
    int ar = tid >> 2, ac = (tid & 3) << 2;
    int br = tid >> 4, bc = (tid & 15) << 2;

    float acc[4][4];
    #pragma unroll
    for (int i = 0; i < 4; i++)
        #pragma unroll
        for (int j = 0; j < 4; j++) acc[i][j] = 0.f;

    for (int k0 = 0; k0 < 256; k0 += 16) {
        float4 va = *(const float4*)(A + (size_t)(blockIdx.x * 64 + ar) * 256 + k0 + ac);
        As[ac + 0][ar] = va.x; As[ac + 1][ar] = va.y;
        As[ac + 2][ar] = va.z; As[ac + 3][ar] = va.w;
        float4 vb = *(const float4*)(B + (size_t)(k0 + br) * 512 + blockIdx.y * 64 + bc);
        *(float4*)&Bs[br][bc] = vb;
        __syncthreads();
        #pragma unroll
        for (int kk = 0; kk < 16; kk++) {
            float a[4], b[4];
            #pragma unroll
            for (int i = 0; i < 4; i++) a[i] = As[kk][ty * 4 + i];
            #pragma unroll
            for (int j = 0; j < 4; j++) b[j] = Bs[kk][tx * 4 + j];
            #pragma unroll
            for (int i = 0; i < 4; i++)
                #pragma unroll
                for (int j = 0; j < 4; j++)
                    acc[i][j] = fmaf(a[i], b[j], acc[i][j]);
        }
        __syncthreads();
    }
    #pragma unroll
    for (int i = 0; i < 4; i++)
        *(float4*)(C + (size_t)(blockIdx.x * 64 + ty * 4 + i) * 512 + blockIdx.y * 64 + tx * 4) =
            *(float4*)acc[i];
}

// ---------------- per-graph softmax + pools (1 block / graph) ----------------
__global__ __launch_bounds__(256)
void pool_kernel(const float* __restrict__ x, const float* __restrict__ s,
                 float* __restrict__ pooled)
{
    __shared__ float red[256];
    __shared__ float w_sm[256];
    int g = blockIdx.x;
    int beg = g_start[g], end = g_start[g + 1];
    if (beg < 0) beg = 0;
    if (end > N_NODES) end = N_NODES;
    int cnt = end - beg;
    int tid = threadIdx.x;

    float m = -3.402823466e38f;
    for (int i = beg + tid; i < end; i += 256) m = fmaxf(m, s[i]);
    red[tid] = m; __syncthreads();
    for (int off = 128; off > 0; off >>= 1) {
        if (tid < off) red[tid] = fmaxf(red[tid], red[tid + off]);
        __syncthreads();
    }
    float smax = red[0];
    __syncthreads();

    float e = 0.f;
    for (int i = beg + tid; i < end; i += 256) e += expf(s[i] - smax);
    red[tid] = e; __syncthreads();
    for (int off = 128; off > 0; off >>= 1) {
        if (tid < off) red[tid] += red[tid + off];
        __syncthreads();
    }
    float inv_den = (cnt > 0) ? (1.f / red[0]) : 0.f;
    __syncthreads();

    float accw = 0.f, accs = 0.f, accm = -3.402823466e38f;
    for (int c0 = beg; c0 < end; c0 += 256) {
        int clen = min(256, end - c0);
        if (tid < clen) w_sm[tid] = expf(s[c0 + tid] - smax) * inv_den;
        __syncthreads();
        #pragma unroll 8
        for (int j = 0; j < clen; j++) {
            float xv = x[(size_t)(c0 + j) * 256 + tid];
            accw = fmaf(w_sm[j], xv, accw);
            accs += xv;
            accm = fmaxf(accm, xv);
        }
        __syncthreads();
    }
    float inv_c = (cnt > 0) ? (1.f / (float)cnt) : 0.f;
    size_t base = (size_t)g * 768;
    pooled[base + tid]       = accs * inv_c;
    pooled[base + 256 + tid] = (cnt > 0) ? accm : 0.f;
    pooled[base + 512 + tid] = (cnt > 0) ? accw : 0.f;
}

// ---------------- fused bias: bf = [bm,bx,bw]@Wc1 + bc1 ----------------
__global__ void bf_kernel(const float* __restrict__ bm, const float* __restrict__ bx,
                          const float* __restrict__ bw, const float* __restrict__ Wc1,
                          const float* __restrict__ bc1)
{
    int c = threadIdx.x;  // 512
    float acc = bc1[c];
    for (int j = 0; j < 256; j++) {
        acc = fmaf(bm[j], Wc1[(size_t)j * 512 + c], acc);
        acc = fmaf(bx[j], Wc1[(size_t)(256 + j) * 512 + c], acc);
        acc = fmaf(bw[j], Wc1[(size_t)(512 + j) * 512 + c], acc);
    }
    g_bf[c] = acc;
}

// ---------------- LayerNorm over rows of [G,256]: warp per row ----------------
__global__ __launch_bounds__(256)
void ln_kernel(const float* __restrict__ y, const float* __restrict__ gamma,
               const float* __restrict__ beta, float* __restrict__ out)
{
    int warp = threadIdx.x >> 5, lane = threadIdx.x & 31;
    int row = blockIdx.x * 8 + warp;
    const float* yr = y + (size_t)row * 256;

    float v[8];
    float sum = 0.f, sq = 0.f;
    #pragma unroll
    for (int j = 0; j < 8; j++) {
        v[j] = yr[lane + 32 * j];
        sum += v[j];
        sq  += v[j] * v[j];
    }
    #pragma unroll
    for (int off = 16; off; off >>= 1) {
        sum += __shfl_xor_sync(0xffffffffu, sum, off);
        sq  += __shfl_xor_sync(0xffffffffu, sq, off);
    }
    float mu  = sum * (1.f / 256.f);
    float var = sq * (1.f / 256.f) - mu * mu;
    float rs  = rsqrtf(var + 1e-5f);
    #pragma unroll
    for (int j = 0; j < 8; j++) {
        int col = lane + 32 * j;
        out[(size_t)row * 256 + col] = (v[j] - mu) * rs * __ldg(&gamma[col]) + __ldg(&beta[col]);
    }
}

// ---------------- launcher ----------------
extern "C" void kernel_launch(void* const* d_in, const int* in_sizes, int n_in,
                              void* d_out, int out_size)
{
    const float* x      = (const float*)d_in[0];
    const int*   batch  = (const int*)d_in[1];
    const float* W_att1 = (const float*)d_in[2];
    const float* b_att1 = (const float*)d_in[3];
    const float* W_att2 = (const float*)d_in[4];
    const float* b_att2 = (const float*)d_in[5];
    const float* Wm     = (const float*)d_in[6];
    const float* bm     = (const float*)d_in[7];
    const float* Wx     = (const float*)d_in[8];
    const float* bx     = (const float*)d_in[9];
    const float* Ww     = (const float*)d_in[10];
    const float* bw     = (const float*)d_in[11];
    const float* Wc1    = (const float*)d_in[12];
    const float* bc1    = (const float*)d_in[13];
    const float* Wc2    = (const float*)d_in[14];
    const float* bc2    = (const float*)d_in[15];
    const float* gamma  = (const float*)d_in[16];
    const float* beta   = (const float*)d_in[17];
    float*       out    = (float*)d_out;

    float *d_s, *d_pooled, *d_Wf, *d_bf, *d_hid, *d_y;
    cudaGetSymbolAddress((void**)&d_s,      g_s);
    cudaGetSymbolAddress((void**)&d_pooled, g_pooled);
    cudaGetSymbolAddress((void**)&d_Wf,     g_Wf);
    cudaGetSymbolAddress((void**)&d_bf,     g_bf);
    cudaGetSymbolAddress((void**)&d_hid,    g_hid);
    cudaGetSymbolAddress((void**)&d_y,      g_y);

    cudaFuncSetAttribute(score_mma_v2,
                         cudaFuncAttributeMaxDynamicSharedMemorySize, SC_SMEM_BYTES);

    // 1. segment starts
    seg_start_kernel<<<N_NODES / 256, 256>>>(batch);

    // 2. fused tail weights
    wf_kernel<<<dim3(4, 8, 3), 256>>>(Wm, Wx, Ww, Wc1, d_Wf);
    bf_kernel<<<1, 512>>>(bm, bx, bw, Wc1, bc1);

    // 3. node attention scores (tf32, cp.async double-buffered)
    score_mma_v2<<<N_NODES / 256, 256, SC_SMEM_BYTES>>>(x, W_att1, b_att1, W_att2, b_att2, d_s);

    // 4. per-graph softmax + pools
    pool_kernel<<<NUM_GRAPHS, 256>>>(x, d_s, d_pooled);

    // 5. hid = gelu(pooled @ Wf + bf)
    gemm_tf32<true, true><<<dim3(NUM_GRAPHS / 128, 4), 256>>>(d_pooled, d_Wf, d_bf, d_hid, 768, 768, 512, 512);

    // 6. y = hid @ Wc2 + bc2  (tf32 tensor cores)
    gemm_tf32<false, true><<<dim3(NUM_GRAPHS / 128, 2), 256>>>(d_hid, Wc2, bc2, d_y, 512, 512, 256, 256);

    // 7. out = LN(y) * gamma + beta
    ln_kernel<<<NUM_GRAPHS / 8, 256>>>(d_y, gamma, beta, out);
}